// round 4
// baseline (speedup 1.0000x reference)
#include <cuda_runtime.h>

#define NN 262144
#define NE 4194304
#define NG 1024
#define CIN 16
#define H 32

// ---------------- scratch (device globals; zero-initialized at load) --------
__device__ __align__(256) float g_h1[NN * H];       // 32 MB
__device__ __align__(256) float g_u[NN * H];        // 32 MB (h1 + agg2)
__device__ __align__(256) float g_t[NN * H];        // 32 MB (transformed)
__device__ __align__(256) float g_gate[NN];
__device__ __align__(256) float g_gmax[NG];
__device__ __align__(256) float g_pooled[NG * H];
__device__ __align__(256) int   g_deg[NN];          // invariant: zero at launch entry
__device__ __align__(256) int   g_off[NN];
__device__ __align__(256) int   g_cursor[NN];
__device__ __align__(256) int   g_csr_src[NE];      // 16 MB
__device__ int g_bsum[256];
__device__ int g_bbase[256];
__device__ int g_gstart[NG + 1];

// ---------------- helpers ---------------------------------------------------
__device__ __forceinline__ void atomicMaxF(float* addr, float v) {
    if (v >= 0.0f) atomicMax((int*)addr, __float_as_int(v));
    else           atomicMin((unsigned int*)addr, __float_as_uint(v));
}

__device__ __forceinline__ unsigned long long pk2(float v) {
    unsigned long long r;
    asm("mov.b64 %0, {%1, %1};" : "=l"(r) : "f"(v));
    return r;
}
__device__ __forceinline__ void fma2(unsigned long long& d, unsigned long long a,
                                     unsigned long long b) {
    asm("fma.rn.f32x2 %0, %1, %2, %0;" : "+l"(d) : "l"(a), "l"(b));
}

template <int K>
__device__ __forceinline__ void mmp(const float* __restrict__ in,
                                    const float* __restrict__ w,
                                    const float* __restrict__ b,
                                    float* __restrict__ out, bool do_relu) {
    unsigned long long acc[16];
#pragma unroll
    for (int c = 0; c < 16; c++) acc[c] = *(const unsigned long long*)(b + 2 * c);
#pragma unroll
    for (int k = 0; k < K; k++) {
        unsigned long long vv = pk2(in[k]);
        const unsigned long long* wr = (const unsigned long long*)(w + k * H);
#pragma unroll
        for (int c = 0; c < 16; c++) fma2(acc[c], vv, wr[c]);
    }
#pragma unroll
    for (int c = 0; c < 16; c++) {
        float lo, hi;
        asm("mov.b64 {%0, %1}, %2;" : "=f"(lo), "=f"(hi) : "l"(acc[c]));
        if (do_relu) { lo = fmaxf(lo, 0.f); hi = fmaxf(hi, 0.f); }
        out[2 * c] = lo; out[2 * c + 1] = hi;
    }
}

// ---------------- CSR build --------------------------------------------------
// deg is zero on entry (module-load zero init; gather2 re-zeroes each launch)
__global__ void k_hist(const int* __restrict__ ei) {
    int e = blockIdx.x * blockDim.x + threadIdx.x;
    if (e < NE) atomicAdd(&g_deg[__ldg(&ei[NE + e])], 1);
}

__global__ void k_scan1() {  // 256 blocks, 1024 elems each -> block sums
    __shared__ int sm[256];
    int t = threadIdx.x;
    int4 d = *(const int4*)&g_deg[blockIdx.x * 1024 + t * 4];
    sm[t] = d.x + d.y + d.z + d.w;
    __syncthreads();
    for (int st = 128; st; st >>= 1) {
        if (t < st) sm[t] += sm[t + st];
        __syncthreads();
    }
    if (t == 0) g_bsum[blockIdx.x] = sm[0];
}

__global__ void k_scan2() {  // 1 block: scan of block sums + gmax init
    __shared__ int sm[256];
    int t = threadIdx.x;
    for (int i = t; i < NG; i += 256) g_gmax[i] = -INFINITY;
    int v = g_bsum[t];
    sm[t] = v;
    __syncthreads();
    for (int st = 1; st < 256; st <<= 1) {
        int a = (t >= st) ? sm[t - st] : 0;
        __syncthreads();
        sm[t] += a;
        __syncthreads();
    }
    g_bbase[t] = sm[t] - v;
}

__global__ void k_scan3() {  // per-block exclusive scan -> offsets + cursor
    __shared__ int sm[256];
    int t = threadIdx.x;
    int base = blockIdx.x * 1024 + t * 4;
    int4 d = *(const int4*)&g_deg[base];
    int s = d.x + d.y + d.z + d.w;
    sm[t] = s;
    __syncthreads();
    for (int st = 1; st < 256; st <<= 1) {
        int a = (t >= st) ? sm[t - st] : 0;
        __syncthreads();
        sm[t] += a;
        __syncthreads();
    }
    int off = g_bbase[blockIdx.x] + sm[t] - s;
    int4 o;
    o.x = off; o.y = off + d.x; o.z = o.y + d.y; o.w = o.z + d.z;
    *(int4*)&g_off[base] = o;
    *(int4*)&g_cursor[base] = o;
}

// fill CSR + graph start offsets (fused; independent work)
__global__ void k_fillg(const int* __restrict__ ei, const int* __restrict__ bv) {
    int e = blockIdx.x * blockDim.x + threadIdx.x;
    if (e < NE) {
        int s = __ldg(&ei[e]);
        int d = __ldg(&ei[NE + e]);
        int p = atomicAdd(&g_cursor[d], 1);
        g_csr_src[p] = s;
    }
    if (e < NN) {
        int b = __ldg(&bv[e]);
        int bp = (e == 0) ? -1 : __ldg(&bv[e - 1]);
        for (int g = bp + 1; g <= b; g++) g_gstart[g] = e;
        if (e == NN - 1)
            for (int g = b + 1; g <= NG; g++) g_gstart[g] = NN;
    }
}

// ---------------- layer 1: gather (fp32) + fused 16x32 GEMM -----------------
// two nodes per warp (16-lane sub-warps); lane l16 = input column;
// after aggregation, sub-warp GEMM via shfl: lane -> output cols 2*l16, 2*l16+1
__global__ void k_gather1(const float* __restrict__ x, const float* __restrict__ w1,
                          const float* __restrict__ b1) {
    __shared__ __align__(16) float sw[CIN * H];
    __shared__ __align__(16) float sb[H];
    for (int i = threadIdx.x; i < CIN * H; i += blockDim.x) sw[i] = w1[i];
    if (threadIdx.x < H) sb[threadIdx.x] = b1[threadIdx.x];
    __syncthreads();
    int warp = (blockIdx.x * blockDim.x + threadIdx.x) >> 5;
    int lane = threadIdx.x & 31;
    int l16 = lane & 15;
    int n = warp * 2 + (lane >> 4);
    int off = g_off[n], deg = g_deg[n];
    float acc = 0.f;
    for (int c = 0; c < deg; c += 16) {
        int idx = c + l16;
        int s = (idx < deg) ? g_csr_src[off + idx] : 0;
        int m = min(16, deg - c);
        int j = 0;
        for (; j + 4 <= m; j += 4) {
            int s0 = __shfl_sync(0xffffffffu, s, j, 16);
            int s1 = __shfl_sync(0xffffffffu, s, j + 1, 16);
            int s2 = __shfl_sync(0xffffffffu, s, j + 2, 16);
            int s3 = __shfl_sync(0xffffffffu, s, j + 3, 16);
            float v0 = __ldg(&x[(long)s0 * CIN + l16]);
            float v1 = __ldg(&x[(long)s1 * CIN + l16]);
            float v2 = __ldg(&x[(long)s2 * CIN + l16]);
            float v3 = __ldg(&x[(long)s3 * CIN + l16]);
            acc += (v0 + v1) + (v2 + v3);
        }
        for (; j < m; j++) {
            int sj = __shfl_sync(0xffffffffu, s, j, 16);
            acc += __ldg(&x[(long)sj * CIN + l16]);
        }
    }
    float in = __ldg(&x[(long)n * CIN + l16]) + acc;   // own node + aggregate
    // sub-warp GEMM: 16 shfl broadcasts, packed fma2
    unsigned long long a64 = *(const unsigned long long*)(sb + 2 * l16);
#pragma unroll
    for (int k = 0; k < CIN; k++) {
        float vk = __shfl_sync(0xffffffffu, in, k, 16);
        fma2(a64, pk2(vk), *(const unsigned long long*)(sw + k * H + 2 * l16));
    }
    float lo, hi;
    asm("mov.b64 {%0, %1}, %2;" : "=f"(lo), "=f"(hi) : "l"(a64));
    float2 o;
    o.x = fmaxf(lo, 0.f);
    o.y = fmaxf(hi, 0.f);
    ((float2*)(g_h1 + (long)n * H))[l16] = o;
}

// ---------------- layer 2: gather + own-row add -> u; resets deg ------------
__global__ void k_gather2() {
    int n = (blockIdx.x * blockDim.x + threadIdx.x) >> 5;
    int lane = threadIdx.x & 31;
    int off = g_off[n], deg = g_deg[n];
    float acc = g_h1[(long)n * H + lane];              // own h1 (u = h1 + agg)
    for (int c = 0; c < deg; c += 32) {
        int idx = c + lane;
        int s = (idx < deg) ? g_csr_src[off + idx] : 0;
        int m = min(32, deg - c);
        int j = 0;
        for (; j + 8 <= m; j += 8) {
            float v = 0.f;
#pragma unroll
            for (int q = 0; q < 8; q++) {
                int sj = __shfl_sync(0xffffffffu, s, j + q);
                v += g_h1[(long)sj * H + lane];
            }
            acc += v;
        }
        for (; j < m; j++) {
            int sj = __shfl_sync(0xffffffffu, s, j);
            acc += g_h1[(long)sj * H + lane];
        }
    }
    g_u[(long)n * H + lane] = acc;
    if (lane == 0) g_deg[n] = 0;    // restore invariant for next launch
}

// layer-2 node update + gate net + transform net + warp-aggregated segment max
__global__ void k_node2(const float* __restrict__ w2, const float* __restrict__ b2,
                        const float* __restrict__ gw1, const float* __restrict__ gb1,
                        const float* __restrict__ gw2, const float* __restrict__ gb2,
                        const float* __restrict__ gw3, const float* __restrict__ gb3,
                        const float* __restrict__ aw1, const float* __restrict__ ab1,
                        const float* __restrict__ aw2, const float* __restrict__ ab2,
                        const int* __restrict__ bv) {
    __shared__ __align__(16) float s_w2[H * H], s_gw1[H * H], s_gw2[H * H];
    __shared__ __align__(16) float s_aw1[H * H], s_aw2[H * H];
    __shared__ __align__(16) float s_b2[H], s_gb1[H], s_gb2[H], s_gw3[H];
    __shared__ __align__(16) float s_ab1[H], s_ab2[H];
    __shared__ float s_gb3;
    for (int i = threadIdx.x; i < H * H; i += blockDim.x) {
        s_w2[i] = w2[i]; s_gw1[i] = gw1[i]; s_gw2[i] = gw2[i];
        s_aw1[i] = aw1[i]; s_aw2[i] = aw2[i];
    }
    if (threadIdx.x < H) {
        s_b2[threadIdx.x] = b2[threadIdx.x];
        s_gb1[threadIdx.x] = gb1[threadIdx.x];
        s_gb2[threadIdx.x] = gb2[threadIdx.x];
        s_gw3[threadIdx.x] = gw3[threadIdx.x];
        s_ab1[threadIdx.x] = ab1[threadIdx.x];
        s_ab2[threadIdx.x] = ab2[threadIdx.x];
    }
    if (threadIdx.x == 0) s_gb3 = gb3[0];
    __syncthreads();
    int n = blockIdx.x * blockDim.x + threadIdx.x;

    float u[H];
#pragma unroll
    for (int q = 0; q < H / 4; q++) {
        float4 a = *(const float4*)(g_u + (long)n * H + q * 4);
        u[q * 4 + 0] = a.x; u[q * 4 + 1] = a.y;
        u[q * 4 + 2] = a.z; u[q * 4 + 3] = a.w;
    }
    float h2[H], t1[H], t2[H];
    mmp<H>(u, s_w2, s_b2, h2, true);

    mmp<H>(h2, s_gw1, s_gb1, t1, true);
    mmp<H>(t1, s_gw2, s_gb2, t2, true);
    float gate = s_gb3;
#pragma unroll
    for (int k = 0; k < H; k++) gate = fmaf(t2[k], s_gw3[k], gate);
    g_gate[n] = gate;

    mmp<H>(h2, s_aw1, s_ab1, t1, true);
    mmp<H>(t1, s_aw2, s_ab2, t2, true);
    float4* o = (float4*)(g_t + (long)n * H);
#pragma unroll
    for (int q = 0; q < H / 4; q++)
        o[q] = make_float4(t2[q * 4], t2[q * 4 + 1], t2[q * 4 + 2], t2[q * 4 + 3]);

    int b = __ldg(&bv[n]);
    int b0 = __shfl_sync(0xffffffffu, b, 0);
    int b31 = __shfl_sync(0xffffffffu, b, 31);
    if (b0 == b31) {
        float m = gate;
#pragma unroll
        for (int st = 16; st; st >>= 1) m = fmaxf(m, __shfl_xor_sync(0xffffffffu, m, st));
        if ((threadIdx.x & 31) == 0) atomicMaxF(&g_gmax[b], m);
    } else {
        atomicMaxF(&g_gmax[b], gate);
    }
}

// ---------------- fused exp + denom + pooled (block per graph) ---------------
__global__ void k_pool() {
    int g = blockIdx.x;
    int start = g_gstart[g], end = g_gstart[g + 1];
    __shared__ float s_red[8][32];
    __shared__ float s_inv;
    int lane = threadIdx.x & 31, w = threadIdx.x >> 5;
    float gm = g_gmax[g];

    float d = 0.f;
    for (int n = start + threadIdx.x; n < end; n += 256) {
        float e = __expf(g_gate[n] - gm);
        g_gate[n] = e;
        d += e;
    }
#pragma unroll
    for (int st = 16; st; st >>= 1) d += __shfl_xor_sync(0xffffffffu, d, st);
    if (lane == 0) s_red[w][0] = d;
    __syncthreads();
    if (threadIdx.x == 0) {
        float t = 0.f;
#pragma unroll
        for (int i = 0; i < 8; i++) t += s_red[i][0];
        s_inv = 1.0f / fmaxf(t, 1e-16f);
    }
    __syncthreads();

    float inv = s_inv;
    float acc = 0.f;
    for (int n = start + w; n < end; n += 8) {
        float a = g_gate[n] * inv;
        acc = fmaf(a, g_t[(long)n * H + lane], acc);
    }
    s_red[w][lane] = acc;
    __syncthreads();
    if (w == 0) {
        float s = 0.f;
#pragma unroll
        for (int i = 0; i < 8; i++) s += s_red[i][lane];
        g_pooled[g * H + lane] = s;
    }
}

// ---------------- critic head ------------------------------------------------
__global__ void k_final(const float* __restrict__ fw1, const float* __restrict__ fb1,
                        const float* __restrict__ fw2, const float* __restrict__ fb2,
                        const float* __restrict__ fw3, const float* __restrict__ fb3,
                        float* __restrict__ out) {
    __shared__ __align__(16) float s_w1[H * H], s_w2[H * H];
    __shared__ __align__(16) float s_b1[H], s_b2[H], s_w3[H];
    __shared__ float s_b3;
    for (int i = threadIdx.x; i < H * H; i += blockDim.x) {
        s_w1[i] = fw1[i]; s_w2[i] = fw2[i];
    }
    if (threadIdx.x < H) {
        s_b1[threadIdx.x] = fb1[threadIdx.x];
        s_b2[threadIdx.x] = fb2[threadIdx.x];
        s_w3[threadIdx.x] = fw3[threadIdx.x];
    }
    if (threadIdx.x == 0) s_b3 = fb3[0];
    __syncthreads();
    int g = blockIdx.x * blockDim.x + threadIdx.x;
    if (g >= NG) return;
    float p[H];
#pragma unroll
    for (int q = 0; q < H / 4; q++) {
        float4 v = *(const float4*)(g_pooled + (long)g * H + q * 4);
        p[q * 4] = v.x; p[q * 4 + 1] = v.y; p[q * 4 + 2] = v.z; p[q * 4 + 3] = v.w;
    }
    float t1[H], t2[H];
    mmp<H>(p, s_w1, s_b1, t1, true);
    mmp<H>(t1, s_w2, s_b2, t2, true);
    float o = s_b3;
#pragma unroll
    for (int k = 0; k < H; k++) o = fmaf(t2[k], s_w3[k], o);
    out[g] = o;
}

// ---------------- launch -----------------------------------------------------
extern "C" void kernel_launch(void* const* d_in, const int* in_sizes, int n_in,
                              void* d_out, int out_size) {
    const float* x   = (const float*)d_in[0];
    const float* w1  = (const float*)d_in[1];
    const float* b1  = (const float*)d_in[2];
    const float* w2  = (const float*)d_in[3];
    const float* b2  = (const float*)d_in[4];
    const float* gw1 = (const float*)d_in[5];
    const float* gb1 = (const float*)d_in[6];
    const float* gw2 = (const float*)d_in[7];
    const float* gb2 = (const float*)d_in[8];
    const float* gw3 = (const float*)d_in[9];
    const float* gb3 = (const float*)d_in[10];
    const float* aw1 = (const float*)d_in[11];
    const float* ab1 = (const float*)d_in[12];
    const float* aw2 = (const float*)d_in[13];
    const float* ab2 = (const float*)d_in[14];
    const float* fw1 = (const float*)d_in[15];
    const float* fb1 = (const float*)d_in[16];
    const float* fw2 = (const float*)d_in[17];
    const float* fb2 = (const float*)d_in[18];
    const float* fw3 = (const float*)d_in[19];
    const float* fb3 = (const float*)d_in[20];
    const int*   ei  = (const int*)d_in[21];
    const int*   bv  = (const int*)d_in[22];
    float* out = (float*)d_out;

    k_hist<<<NE / 256, 256>>>(ei);
    k_scan1<<<256, 256>>>();
    k_scan2<<<1, 256>>>();
    k_scan3<<<256, 256>>>();
    k_fillg<<<NE / 256, 256>>>(ei, bv);

    k_gather1<<<NN / 16, 256>>>(x, w1, b1);   // 2 nodes/warp, fused node1 GEMM
    k_gather2<<<NN / 8, 256>>>();             // 1 node/warp, writes u, resets deg
    k_node2<<<NN / 128, 128>>>(w2, b2, gw1, gb1, gw2, gb2, gw3, gb3,
                               aw1, ab1, aw2, ab2, bv);
    k_pool<<<NG, 256>>>();
    k_final<<<NG / 256, 256>>>(fw1, fb1, fw2, fb2, fw3, fb3, out);
}

// round 5
// speedup vs baseline: 1.1897x; 1.1897x over previous
#include <cuda_runtime.h>

#define NN 262144
#define NE 4194304
#define NG 1024
#define CIN 16
#define H 32

// ---------------- scratch (device globals; no allocation allowed) ----------
__device__ __align__(256) float g_agg1[NN * CIN];   // 16 MB
__device__ __align__(256) float g_h1[NN * H];       // 32 MB
__device__ __align__(256) float g_agg2[NN * H];     // 32 MB
__device__ __align__(256) float g_t[NN * H];        // 32 MB (transformed features)
__device__ __align__(256) float g_gate[NN];         // gate score, then e
__device__ __align__(256) float g_gmax[NG];
__device__ __align__(256) float g_pooled[NG * H];
__device__ __align__(256) int   g_deg[NN];
__device__ __align__(256) int   g_off[NN];
__device__ __align__(256) int   g_cursor[NN];
__device__ __align__(256) int   g_csr_src[NE];      // 16 MB
__device__ int g_bsum[256];
__device__ int g_bbase[256];
__device__ int g_gstart[NG + 1];

// ---------------- helpers ---------------------------------------------------
__device__ __forceinline__ void atomicMaxF(float* addr, float v) {
    if (v >= 0.0f) atomicMax((int*)addr, __float_as_int(v));
    else           atomicMin((unsigned int*)addr, __float_as_uint(v));
}

__device__ __forceinline__ unsigned long long pk2(float v) {
    unsigned long long r;
    asm("mov.b64 %0, {%1, %1};" : "=l"(r) : "f"(v));
    return r;
}
__device__ __forceinline__ void fma2(unsigned long long& d, unsigned long long a,
                                     unsigned long long b) {
    asm("fma.rn.f32x2 %0, %1, %2, %0;" : "+l"(d) : "l"(a), "l"(b));
}

// K x 32 dense layer, packed f32x2 FMA; w,b in (16B-aligned) shared memory
template <int K>
__device__ __forceinline__ void mmp(const float* __restrict__ in,
                                    const float* __restrict__ w,
                                    const float* __restrict__ b,
                                    float* __restrict__ out, bool do_relu) {
    unsigned long long acc[16];
#pragma unroll
    for (int c = 0; c < 16; c++) acc[c] = *(const unsigned long long*)(b + 2 * c);
#pragma unroll
    for (int k = 0; k < K; k++) {
        unsigned long long vv = pk2(in[k]);
        const unsigned long long* wr = (const unsigned long long*)(w + k * H);
#pragma unroll
        for (int c = 0; c < 16; c++) fma2(acc[c], vv, wr[c]);
    }
#pragma unroll
    for (int c = 0; c < 16; c++) {
        float lo, hi;
        asm("mov.b64 {%0, %1}, %2;" : "=f"(lo), "=f"(hi) : "l"(acc[c]));
        if (do_relu) { lo = fmaxf(lo, 0.f); hi = fmaxf(hi, 0.f); }
        out[2 * c] = lo; out[2 * c + 1] = hi;
    }
}

// ---------------- CSR build --------------------------------------------------
__global__ void k_init() {  // 256 blocks x 256 threads
    int i = blockIdx.x * blockDim.x + threadIdx.x;      // 65536 threads
    ((int4*)g_deg)[i] = make_int4(0, 0, 0, 0);          // 262144 ints
    if (i < NG) g_gmax[i] = -INFINITY;
}

__global__ void k_hist(const int* __restrict__ ei) {   // 2 edges/thread
    int i = blockIdx.x * blockDim.x + threadIdx.x;
    if (i < NE / 2) {
        int2 d = __ldg((const int2*)(ei + NE) + i);
        atomicAdd(&g_deg[d.x], 1);
        atomicAdd(&g_deg[d.y], 1);
    }
}

__global__ void k_scan1() {  // 256 blocks, 1024 elems each -> block sums
    __shared__ int sm[256];
    int t = threadIdx.x;
    int4 d = *(const int4*)&g_deg[blockIdx.x * 1024 + t * 4];
    sm[t] = d.x + d.y + d.z + d.w;
    __syncthreads();
    for (int st = 128; st; st >>= 1) {
        if (t < st) sm[t] += sm[t + st];
        __syncthreads();
    }
    if (t == 0) g_bsum[blockIdx.x] = sm[0];
}

__global__ void k_scan2() {  // 1 block: exclusive scan of 256 block sums
    __shared__ int sm[256];
    int t = threadIdx.x;
    int v = g_bsum[t];
    sm[t] = v;
    __syncthreads();
    for (int st = 1; st < 256; st <<= 1) {
        int a = (t >= st) ? sm[t - st] : 0;
        __syncthreads();
        sm[t] += a;
        __syncthreads();
    }
    g_bbase[t] = sm[t] - v;
}

__global__ void k_scan3() {  // per-block exclusive scan -> offsets + cursor
    __shared__ int sm[256];
    int t = threadIdx.x;
    int base = blockIdx.x * 1024 + t * 4;
    int4 d = *(const int4*)&g_deg[base];
    int s = d.x + d.y + d.z + d.w;
    sm[t] = s;
    __syncthreads();
    for (int st = 1; st < 256; st <<= 1) {
        int a = (t >= st) ? sm[t - st] : 0;
        __syncthreads();
        sm[t] += a;
        __syncthreads();
    }
    int off = g_bbase[blockIdx.x] + sm[t] - s;
    int4 o;
    o.x = off; o.y = off + d.x; o.z = o.y + d.y; o.w = o.z + d.z;
    *(int4*)&g_off[base] = o;
    *(int4*)&g_cursor[base] = o;
}

// fill CSR + graph start offsets (fused; independent work)
__global__ void k_fillg(const int* __restrict__ ei, const int* __restrict__ bv) {
    int e = blockIdx.x * blockDim.x + threadIdx.x;
    if (e < NE) {
        int s = __ldg(&ei[e]);
        int d = __ldg(&ei[NE + e]);
        int p = atomicAdd(&g_cursor[d], 1);
        g_csr_src[p] = s;
    }
    if (e < NN) {
        int b = __ldg(&bv[e]);
        int bp = (e == 0) ? -1 : __ldg(&bv[e - 1]);
        for (int g = bp + 1; g <= b; g++) g_gstart[g] = e;
        if (e == NN - 1)
            for (int g = b + 1; g <= NG; g++) g_gstart[g] = NN;
    }
}

// ---------------- aggregation (gather, no atomics) --------------------------
// layer 1: two nodes per warp (16-lane sub-warps), x rows are 64B
__global__ void k_gather1(const float* __restrict__ x) {
    int warp = (blockIdx.x * blockDim.x + threadIdx.x) >> 5;
    int lane = threadIdx.x & 31;
    int l16 = lane & 15;
    int n = warp * 2 + (lane >> 4);
    int off = g_off[n], deg = g_deg[n];
    float acc = 0.f;
    for (int c = 0; c < deg; c += 16) {
        int idx = c + l16;
        int s = (idx < deg) ? g_csr_src[off + idx] : 0;
        int m = min(16, deg - c);
        int j = 0;
        for (; j + 4 <= m; j += 4) {
            int s0 = __shfl_sync(0xffffffffu, s, j, 16);
            int s1 = __shfl_sync(0xffffffffu, s, j + 1, 16);
            int s2 = __shfl_sync(0xffffffffu, s, j + 2, 16);
            int s3 = __shfl_sync(0xffffffffu, s, j + 3, 16);
            float v0 = __ldg(&x[s0 * CIN + l16]);
            float v1 = __ldg(&x[s1 * CIN + l16]);
            float v2 = __ldg(&x[s2 * CIN + l16]);
            float v3 = __ldg(&x[s3 * CIN + l16]);
            acc += (v0 + v1) + (v2 + v3);
        }
        for (; j < m; j++) {
            int sj = __shfl_sync(0xffffffffu, s, j, 16);
            acc += __ldg(&x[sj * CIN + l16]);
        }
    }
    g_agg1[n * CIN + l16] = acc;
}

// layer 2: one node per warp, h1 rows are 128B
__global__ void k_gather2() {
    int n = (blockIdx.x * blockDim.x + threadIdx.x) >> 5;
    int lane = threadIdx.x & 31;
    int off = g_off[n], deg = g_deg[n];
    float acc = 0.f;
    for (int c = 0; c < deg; c += 32) {
        int idx = c + lane;
        int s = (idx < deg) ? g_csr_src[off + idx] : 0;
        int m = min(32, deg - c);
        int j = 0;
        for (; j + 8 <= m; j += 8) {
            float v = 0.f;
#pragma unroll
            for (int q = 0; q < 8; q++) {
                int sj = __shfl_sync(0xffffffffu, s, j + q);
                v += g_h1[sj * H + lane];
            }
            acc += v;
        }
        for (; j < m; j++) {
            int sj = __shfl_sync(0xffffffffu, s, j);
            acc += g_h1[sj * H + lane];
        }
    }
    g_agg2[n * H + lane] = acc;
}

// ---------------- node-wise dense chains -------------------------------------
__global__ void k_node1(const float* __restrict__ x, const float* __restrict__ w1,
                        const float* __restrict__ b1) {
    __shared__ __align__(16) float sw[CIN * H];
    __shared__ __align__(16) float sb[H];
    for (int i = threadIdx.x; i < CIN * H; i += blockDim.x) sw[i] = w1[i];
    if (threadIdx.x < H) sb[threadIdx.x] = b1[threadIdx.x];
    __syncthreads();
    int n = blockIdx.x * blockDim.x + threadIdx.x;
    float in[CIN];
#pragma unroll
    for (int q = 0; q < CIN / 4; q++) {
        float4 a = __ldg((const float4*)(x + (long)n * CIN + q * 4));
        float4 b = *(const float4*)(g_agg1 + (long)n * CIN + q * 4);
        in[q * 4 + 0] = a.x + b.x; in[q * 4 + 1] = a.y + b.y;
        in[q * 4 + 2] = a.z + b.z; in[q * 4 + 3] = a.w + b.w;
    }
    float h[H];
    mmp<CIN>(in, sw, sb, h, true);
    float4* o = (float4*)(g_h1 + (long)n * H);
#pragma unroll
    for (int q = 0; q < H / 4; q++)
        o[q] = make_float4(h[q * 4], h[q * 4 + 1], h[q * 4 + 2], h[q * 4 + 3]);
}

// layer-2 node update + gate net + transform net + warp-aggregated segment max
__global__ void k_node2(const float* __restrict__ w2, const float* __restrict__ b2,
                        const float* __restrict__ gw1, const float* __restrict__ gb1,
                        const float* __restrict__ gw2, const float* __restrict__ gb2,
                        const float* __restrict__ gw3, const float* __restrict__ gb3,
                        const float* __restrict__ aw1, const float* __restrict__ ab1,
                        const float* __restrict__ aw2, const float* __restrict__ ab2,
                        const int* __restrict__ bv) {
    __shared__ __align__(16) float s_w2[H * H], s_gw1[H * H], s_gw2[H * H];
    __shared__ __align__(16) float s_aw1[H * H], s_aw2[H * H];
    __shared__ __align__(16) float s_b2[H], s_gb1[H], s_gb2[H], s_gw3[H];
    __shared__ __align__(16) float s_ab1[H], s_ab2[H];
    __shared__ float s_gb3;
    for (int i = threadIdx.x; i < H * H; i += blockDim.x) {
        s_w2[i] = w2[i]; s_gw1[i] = gw1[i]; s_gw2[i] = gw2[i];
        s_aw1[i] = aw1[i]; s_aw2[i] = aw2[i];
    }
    if (threadIdx.x < H) {
        s_b2[threadIdx.x] = b2[threadIdx.x];
        s_gb1[threadIdx.x] = gb1[threadIdx.x];
        s_gb2[threadIdx.x] = gb2[threadIdx.x];
        s_gw3[threadIdx.x] = gw3[threadIdx.x];
        s_ab1[threadIdx.x] = ab1[threadIdx.x];
        s_ab2[threadIdx.x] = ab2[threadIdx.x];
    }
    if (threadIdx.x == 0) s_gb3 = gb3[0];
    __syncthreads();
    int n = blockIdx.x * blockDim.x + threadIdx.x;

    float u[H];
#pragma unroll
    for (int q = 0; q < H / 4; q++) {
        float4 a = *(const float4*)(g_h1 + (long)n * H + q * 4);
        float4 b = *(const float4*)(g_agg2 + (long)n * H + q * 4);
        u[q * 4 + 0] = a.x + b.x; u[q * 4 + 1] = a.y + b.y;
        u[q * 4 + 2] = a.z + b.z; u[q * 4 + 3] = a.w + b.w;
    }
    float h2[H], t1[H], t2[H];
    mmp<H>(u, s_w2, s_b2, h2, true);

    // gate network
    mmp<H>(h2, s_gw1, s_gb1, t1, true);
    mmp<H>(t1, s_gw2, s_gb2, t2, true);
    float gate = s_gb3;
#pragma unroll
    for (int k = 0; k < H; k++) gate = fmaf(t2[k], s_gw3[k], gate);
    g_gate[n] = gate;

    // transform network: store t
    mmp<H>(h2, s_aw1, s_ab1, t1, true);
    mmp<H>(t1, s_aw2, s_ab2, t2, true);
    float4* o = (float4*)(g_t + (long)n * H);
#pragma unroll
    for (int q = 0; q < H / 4; q++)
        o[q] = make_float4(t2[q * 4], t2[q * 4 + 1], t2[q * 4 + 2], t2[q * 4 + 3]);

    // segment max (bv sorted -> most warps uniform)
    int b = __ldg(&bv[n]);
    int b0 = __shfl_sync(0xffffffffu, b, 0);
    int b31 = __shfl_sync(0xffffffffu, b, 31);
    if (b0 == b31) {
        float m = gate;
#pragma unroll
        for (int st = 16; st; st >>= 1) m = fmaxf(m, __shfl_xor_sync(0xffffffffu, m, st));
        if ((threadIdx.x & 31) == 0) atomicMaxF(&g_gmax[b], m);
    } else {
        atomicMaxF(&g_gmax[b], gate);
    }
}

// ---------------- fused exp + denom + pooled (block per graph) ---------------
__global__ void k_pool() {
    int g = blockIdx.x;
    int start = g_gstart[g], end = g_gstart[g + 1];
    __shared__ float s_red[8][32];
    __shared__ float s_inv;
    int lane = threadIdx.x & 31, w = threadIdx.x >> 5;
    float gm = g_gmax[g];

    float d = 0.f;
    for (int n = start + threadIdx.x; n < end; n += 256) {
        float e = __expf(g_gate[n] - gm);
        g_gate[n] = e;
        d += e;
    }
#pragma unroll
    for (int st = 16; st; st >>= 1) d += __shfl_xor_sync(0xffffffffu, d, st);
    if (lane == 0) s_red[w][0] = d;
    __syncthreads();
    if (threadIdx.x == 0) {
        float t = 0.f;
#pragma unroll
        for (int i = 0; i < 8; i++) t += s_red[i][0];
        s_inv = 1.0f / fmaxf(t, 1e-16f);
    }
    __syncthreads();

    float inv = s_inv;
    float acc = 0.f;
    for (int n = start + w; n < end; n += 8) {
        float a = g_gate[n] * inv;
        acc = fmaf(a, g_t[(long)n * H + lane], acc);
    }
    s_red[w][lane] = acc;
    __syncthreads();
    if (w == 0) {
        float s = 0.f;
#pragma unroll
        for (int i = 0; i < 8; i++) s += s_red[i][lane];
        g_pooled[g * H + lane] = s;
    }
}

// ---------------- critic head ------------------------------------------------
__global__ void k_final(const float* __restrict__ fw1, const float* __restrict__ fb1,
                        const float* __restrict__ fw2, const float* __restrict__ fb2,
                        const float* __restrict__ fw3, const float* __restrict__ fb3,
                        float* __restrict__ out) {
    __shared__ __align__(16) float s_w1[H * H], s_w2[H * H];
    __shared__ __align__(16) float s_b1[H], s_b2[H], s_w3[H];
    __shared__ float s_b3;
    for (int i = threadIdx.x; i < H * H; i += blockDim.x) {
        s_w1[i] = fw1[i]; s_w2[i] = fw2[i];
    }
    if (threadIdx.x < H) {
        s_b1[threadIdx.x] = fb1[threadIdx.x];
        s_b2[threadIdx.x] = fb2[threadIdx.x];
        s_w3[threadIdx.x] = fw3[threadIdx.x];
    }
    if (threadIdx.x == 0) s_b3 = fb3[0];
    __syncthreads();
    int g = blockIdx.x * blockDim.x + threadIdx.x;
    if (g >= NG) return;
    float p[H];
#pragma unroll
    for (int q = 0; q < H / 4; q++) {
        float4 v = *(const float4*)(g_pooled + (long)g * H + q * 4);
        p[q * 4] = v.x; p[q * 4 + 1] = v.y; p[q * 4 + 2] = v.z; p[q * 4 + 3] = v.w;
    }
    float t1[H], t2[H];
    mmp<H>(p, s_w1, s_b1, t1, true);
    mmp<H>(t1, s_w2, s_b2, t2, true);
    float o = s_b3;
#pragma unroll
    for (int k = 0; k < H; k++) o = fmaf(t2[k], s_w3[k], o);
    out[g] = o;
}

// ---------------- launch -----------------------------------------------------
extern "C" void kernel_launch(void* const* d_in, const int* in_sizes, int n_in,
                              void* d_out, int out_size) {
    const float* x   = (const float*)d_in[0];
    const float* w1  = (const float*)d_in[1];
    const float* b1  = (const float*)d_in[2];
    const float* w2  = (const float*)d_in[3];
    const float* b2  = (const float*)d_in[4];
    const float* gw1 = (const float*)d_in[5];
    const float* gb1 = (const float*)d_in[6];
    const float* gw2 = (const float*)d_in[7];
    const float* gb2 = (const float*)d_in[8];
    const float* gw3 = (const float*)d_in[9];
    const float* gb3 = (const float*)d_in[10];
    const float* aw1 = (const float*)d_in[11];
    const float* ab1 = (const float*)d_in[12];
    const float* aw2 = (const float*)d_in[13];
    const float* ab2 = (const float*)d_in[14];
    const float* fw1 = (const float*)d_in[15];
    const float* fb1 = (const float*)d_in[16];
    const float* fw2 = (const float*)d_in[17];
    const float* fb2 = (const float*)d_in[18];
    const float* fw3 = (const float*)d_in[19];
    const float* fb3 = (const float*)d_in[20];
    const int*   ei  = (const int*)d_in[21];
    const int*   bv  = (const int*)d_in[22];
    float* out = (float*)d_out;

    k_init<<<256, 256>>>();
    k_hist<<<NE / 512, 256>>>(ei);
    k_scan1<<<256, 256>>>();
    k_scan2<<<1, 256>>>();
    k_scan3<<<256, 256>>>();
    k_fillg<<<NE / 256, 256>>>(ei, bv);

    k_gather1<<<NN / 16, 256>>>(x);           // 2 nodes/warp, 8 warps/block
    k_node1<<<NN / 256, 256>>>(x, w1, b1);
    k_gather2<<<NN / 8, 256>>>();             // 1 node/warp
    k_node2<<<NN / 128, 128>>>(w2, b2, gw1, gb1, gw2, gb2, gw3, gb3,
                               aw1, ab1, aw2, ab2, bv);
    k_pool<<<NG, 256>>>();
    k_final<<<NG / 256, 256>>>(fw1, fb1, fw2, fb2, fw3, fb3, out);
}